// round 13
// baseline (speedup 1.0000x reference)
#include <cuda_runtime.h>
#include <cstdint>

// Problem constants
#define T_STEPS 2048
#define B_TOT   256
#define H_DIM   512
#define D_IN    529
#define KPAD    544            // padded K cols = 34 k16-steps
#define KSTEPS  34
#define ROWS_PER_CTA 64
#define B_PER_CL 16
#define NCL 16
#define NTHREADS 512
#define XROW 20

// SMEM word (uint32) offsets
#define W_WORDS (2*8*KSTEPS*32*2)     // 2 terms x 8 ntiles x 34 ks x 32 lanes x 2 regs = 34816
#define A_WORDS (2*KSTEPS*32*4)       // 2 terms x 34 ks x 32 lanes x 4 regs = 8704
#define OFF_W 0
#define OFF_A (OFF_W + W_WORDS)
#define OFF_WO (OFF_A + A_WORDS)      // float[KPAD]
#define OFF_XC (OFF_WO + KPAD)        // float[2*16*XROW]
#define SMEM_WORDS (OFF_XC + 2*B_PER_CL*XROW)

#define W_WORD(term,nt,ks,ln,reg) (((((term)*8+(nt))*KSTEPS+(ks))*32+(ln))*2+(reg))
#define A2W(t2,ks,ln) ((((t2)*KSTEPS+(ks))*32+(ln))*4)

// f32 hidden ping-pong (for o_t and h_final)
__device__ float g_hbuf[2][B_TOT * H_DIM];
// fragment-ready bf16 2-term hidden ping-pong: [pp][cluster][term][32 blk x 32 lanes x 4 regs]
__device__ uint32_t g_hfrag[2][NCL][2][4096];

__device__ __forceinline__ uint32_t f2bf(float f) {
    uint32_t u = __float_as_uint(f);
    return (u + 0x7FFFu + ((u >> 16) & 1u)) >> 16;
}
__device__ __forceinline__ float bf2f(uint32_t b) { return __uint_as_float(b << 16); }

// pack {lo=bf16(a), hi=bf16(b)} in one HW cvt
__device__ __forceinline__ uint32_t cvt2(float a, float b) {
    uint32_t r;
    asm("cvt.rn.satfinite.bf16x2.f32 %0, %1, %2;" : "=r"(r) : "f"(b), "f"(a));
    return r;
}

__device__ __forceinline__ void mma16816(float c[4], uint4 a, uint2 b) {
    asm volatile(
        "mma.sync.aligned.m16n8k16.row.col.f32.bf16.bf16.f32 "
        "{%0,%1,%2,%3}, {%4,%5,%6,%7}, {%8,%9}, {%0,%1,%2,%3};"
        : "+f"(c[0]), "+f"(c[1]), "+f"(c[2]), "+f"(c[3])
        : "r"(a.x), "r"(a.y), "r"(a.z), "r"(a.w), "r"(b.x), "r"(b.y));
}

// split float2 into two packed bf16x2 terms
__device__ __forceinline__ void split2(float v0, float v1, uint32_t& q0, uint32_t& q1) {
    q0 = cvt2(v0, v1);
    float e0 = v0 - __uint_as_float(q0 << 16);
    float e1 = v1 - __uint_as_float(q0 & 0xFFFF0000u);
    q1 = cvt2(e0, e1);
}

extern "C" __global__ void __launch_bounds__(NTHREADS, 1) __cluster_dims__(8, 1, 1)
rnn_mma_kernel(const float* __restrict__ x,       // [B, T, 16]
               const float* __restrict__ hidden,  // [B, 512]
               const float* __restrict__ cost,    // [B, T]
               const float* __restrict__ Wo,      // [1, 529]
               const float* __restrict__ Wh,      // [512, 529]
               float* __restrict__ out)           // [B*T] outs, then [B*512] h_final
{
    extern __shared__ uint32_t smw[];
    float* WoS  = (float*)(smw + OFF_WO);
    float* xcb  = (float*)(smw + OFF_XC);

    const int tid   = threadIdx.x;
    const int lane  = tid & 31;
    const int w     = tid >> 5;                 // warp 0..15
    const int crank = blockIdx.x & 7;
    const int clid  = blockIdx.x >> 3;
    const int bbase = clid * B_PER_CL;
    const int row0  = crank * ROWS_PER_CTA;

    // ---- one-time: W 2-term bf16 split into fragment-ordered SMEM ----
    for (int idx = tid; idx < ROWS_PER_CTA * KPAD; idx += NTHREADS) {
        int nl = idx / KPAD, c = idx - nl * KPAD;
        float v = (c < D_IN) ? Wh[(size_t)(row0 + nl) * D_IN + c] : 0.0f;
        uint32_t b0 = f2bf(v);
        uint32_t b1 = f2bf(v - bf2f(b0));
        int nt = nl >> 3, gp = nl & 7, ks = c >> 4, kk = c & 15;
        int reg = kk >> 3, tpp = (kk & 7) >> 1, half = kk & 1, lnp = gp * 4 + tpp;
        ((uint16_t*)smw)[(OFF_W + W_WORD(0, nt, ks, lnp, reg)) * 2 + half] = (uint16_t)b0;
        ((uint16_t*)smw)[(OFF_W + W_WORD(1, nt, ks, lnp, reg)) * 2 + half] = (uint16_t)b1;
    }
    for (int idx = tid; idx < A_WORDS; idx += NTHREADS) smw[OFF_A + idx] = 0u;
    for (int idx = tid; idx < KPAD; idx += NTHREADS) WoS[idx] = (idx < D_IN) ? Wo[idx] : 0.0f;
    // f32 h0 for o_t
    for (int idx = tid; idx < 2 * H_DIM; idx += NTHREADS) {
        int bl = idx >> 9, col = idx & (H_DIM - 1);
        size_t off = (size_t)(bbase + crank * 2 + bl) * H_DIM + col;
        g_hbuf[1][off] = hidden[off];
    }
    // frag-form h0: this CTA's 64-row slice
    {
        int m = tid >> 5, n0 = (tid & 31) * 2;
        float v0 = hidden[(size_t)(bbase + m) * H_DIM + row0 + n0];
        float v1 = hidden[(size_t)(bbase + m) * H_DIM + row0 + n0 + 1];
        uint32_t q0, q1;
        split2(v0, v1, q0, q1);
        int lane2 = (m & 7) * 4 + ((n0 >> 1) & 3);
        int rr = (m >> 3) | (((n0 >> 3) & 1) << 1);
        int widx = (row0 >> 4) * 128 + (((n0 >> 4) * 32 + lane2) * 4 + rr);
        g_hfrag[1][clid][0][widx] = q0;
        g_hfrag[1][clid][1][widx] = q1;
    }
    // x/cost t=0
    if (tid < 128) {
        int b = tid >> 3, q = tid & 7;
        const float* xp = x + ((size_t)(bbase + b) * T_STEPS) * 16;
        xcb[b * XROW + 2 * q]     = __ldg(xp + 2 * q);
        xcb[b * XROW + 2 * q + 1] = __ldg(xp + 2 * q + 1);
        if (q == 0) xcb[b * XROW + 16] = __ldg(cost + (size_t)(bbase + b) * T_STEPS);
    }
    __syncthreads();
    asm volatile("barrier.cluster.arrive.aligned;" ::: "memory");
    asm volatile("barrier.cluster.wait.aligned;"   ::: "memory");

    const int nt = w;             // mma warps 0..7: n-tile (8 rows), all 34 ksteps

    for (int t = 0; t < T_STEPS; ++t) {
        const int ppr = (t + 1) & 1, ppw = t & 1, cur = t & 1;
        const float* xcc = xcb + cur * B_PER_CL * XROW;

        // ---- phase A: staging copy, all 512 threads (2048 uint4 = 4/thread) ----
        {
            const uint4* gsrc = (const uint4*)g_hfrag[ppr][clid];
            uint4 v[4];
            #pragma unroll
            for (int i = 0; i < 4; ++i) v[i] = __ldcg(gsrc + tid + 512 * i);
            #pragma unroll
            for (int i = 0; i < 4; ++i) {
                int q = tid + 512 * i;
                int t2 = q >> 10, qq = q & 1023;
                *(uint4*)&smw[OFF_A + (t2 * KSTEPS + 1) * 128 + qq * 4] = v[i];
            }
        }
        // x frags (ks0) and cost frags (ks33)
        if (tid < 128) {
            int m = tid >> 3, p = tid & 7;
            uint32_t q0, q1;
            split2(xcc[m * XROW + 2 * p], xcc[m * XROW + 2 * p + 1], q0, q1);
            int lane2 = (m & 7) * 4 + (p & 3);
            int rr = (m >> 3) | ((p >> 2) << 1);
            int wi = lane2 * 4 + rr;
            smw[OFF_A + wi] = q0;
            smw[OFF_A + KSTEPS * 128 + wi] = q1;
        } else if (tid < 144) {
            int m = tid - 128;
            uint32_t q0, q1;
            split2(xcc[m * XROW + 16], 0.0f, q0, q1);
            int wi = 33 * 128 + ((m & 7) * 4) * 4 + (m >> 3);
            smw[OFF_A + wi] = q0;
            smw[OFF_A + KSTEPS * 128 + wi] = q1;
        }
        __syncthreads();

        // ---- phase B ----
        if (w < 8) {
            // mma warp nt: all 34 ksteps, 8 independent acc chains (4 passes x 2 k-ranges)
            float a0[4][4], a1[4][4];
            #pragma unroll
            for (int p = 0; p < 4; ++p)
                #pragma unroll
                for (int i = 0; i < 4; ++i) { a0[p][i] = 0.0f; a1[p][i] = 0.0f; }

            #pragma unroll
            for (int s = 0; s < 17; ++s) {
                uint4 I0 = *(const uint4*)&smw[OFF_A + A2W(0, s, lane)];
                uint4 I1 = *(const uint4*)&smw[OFF_A + A2W(1, s, lane)];
                uint2 W0 = *(const uint2*)&smw[OFF_W + W_WORD(0, nt, s, lane, 0)];
                uint2 W1 = *(const uint2*)&smw[OFF_W + W_WORD(1, nt, s, lane, 0)];
                mma16816(a0[0], I0, W0);
                mma16816(a0[1], I1, W0);
                mma16816(a0[2], I0, W1);
                mma16816(a0[3], I1, W1);
            }
            #pragma unroll
            for (int s = 17; s < 34; ++s) {
                uint4 I0 = *(const uint4*)&smw[OFF_A + A2W(0, s, lane)];
                uint4 I1 = *(const uint4*)&smw[OFF_A + A2W(1, s, lane)];
                uint2 W0 = *(const uint2*)&smw[OFF_W + W_WORD(0, nt, s, lane, 0)];
                uint2 W1 = *(const uint2*)&smw[OFF_W + W_WORD(1, nt, s, lane, 0)];
                mma16816(a1[0], I0, W0);
                mma16816(a1[1], I1, W0);
                mma16816(a1[2], I0, W1);
                mma16816(a1[3], I1, W1);
            }
            float s4[4];
            #pragma unroll
            for (int i = 0; i < 4; ++i)
                s4[i] = ((a0[0][i] + a0[1][i]) + (a0[2][i] + a0[3][i]))
                      + ((a1[0][i] + a1[1][i]) + (a1[2][i] + a1[3][i]));

            // direct publish: C-frag == next-step A-frag (same lane, regs 2*(nt&1)+{0,1})
            int b = lane >> 2, j = lane & 3;
            uint32_t t0a, t1a, t0b, t1b;
            split2(s4[0], s4[1], t0a, t1a);    // batch b,   cols 2j,2j+1
            split2(s4[2], s4[3], t0b, t1b);    // batch b+8
            int base = ((crank * 4 + (nt >> 1)) * 32 + lane) * 4 + (nt & 1) * 2;
            __stcg((uint2*)&g_hfrag[ppw][clid][0][base], make_uint2(t0a, t0b));
            __stcg((uint2*)&g_hfrag[ppw][clid][1][base], make_uint2(t1a, t1b));

            float* hdst = (t == T_STEPS - 1) ? (out + (size_t)B_TOT * T_STEPS) : g_hbuf[ppw];
            int col = row0 + nt * 8 + 2 * j;
            __stcg((float2*)(hdst + (size_t)(bbase + b) * H_DIM + col),     make_float2(s4[0], s4[1]));
            __stcg((float2*)(hdst + (size_t)(bbase + b + 8) * H_DIM + col), make_float2(s4[2], s4[3]));
        } else if (w == 15) {
            // o_t (pre-update h, f32), concurrent with mma
            int bo = 2 * crank + (lane >> 4), li = lane & 15;
            const float* hrow = g_hbuf[ppr] + (size_t)(bbase + bo) * H_DIM;
            float r = 0.0f;
            #pragma unroll
            for (int j = 0; j < KSTEPS; ++j) {
                int c = li + 16 * j;
                float v;
                if (c < 16)        v = xcc[bo * XROW + c];
                else if (c < 528)  v = __ldcg(hrow + (c - 16));
                else if (c == 528) v = xcc[bo * XROW + 16];
                else               v = 0.0f;
                r += WoS[c] * v;
            }
            r += __shfl_xor_sync(0xffffffffu, r, 1);
            r += __shfl_xor_sync(0xffffffffu, r, 2);
            r += __shfl_xor_sync(0xffffffffu, r, 4);
            r += __shfl_xor_sync(0xffffffffu, r, 8);
            if (li == 0) out[(size_t)(bbase + bo) * T_STEPS + t] = r;
        } else {
            // warps 8-14: prefetch x/cost for t+1 (concurrent with mma)
            int t2 = tid - 256;
            if (t2 < 128 && t + 1 < T_STEPS) {
                int b = t2 >> 3, q = t2 & 7;
                float* dst = xcb + ((t + 1) & 1) * B_PER_CL * XROW + b * XROW;
                const float* xp = x + ((size_t)(bbase + b) * T_STEPS + (t + 1)) * 16;
                dst[2 * q]     = __ldg(xp + 2 * q);
                dst[2 * q + 1] = __ldg(xp + 2 * q + 1);
                if (q == 0) dst[16] = __ldg(cost + (size_t)(bbase + b) * T_STEPS + (t + 1));
            }
        }

        // ---- cluster barrier: publish h_{t+1} before next step reads ----
        asm volatile("barrier.cluster.arrive.aligned;" ::: "memory");
        asm volatile("barrier.cluster.wait.aligned;"   ::: "memory");
    }
}

extern "C" void kernel_launch(void* const* d_in, const int* in_sizes, int n_in,
                              void* d_out, int out_size) {
    const float* x      = (const float*)d_in[0];
    const float* hidden = (const float*)d_in[1];
    const float* cost   = (const float*)d_in[2];
    const float* Wo     = (const float*)d_in[3];
    const float* Wh     = (const float*)d_in[4];
    float* out = (float*)d_out;

    size_t smem = (size_t)SMEM_WORDS * 4;   // ~175 KB
    cudaFuncSetAttribute(rnn_mma_kernel, cudaFuncAttributeMaxDynamicSharedMemorySize, (int)smem);
    rnn_mma_kernel<<<128, NTHREADS, smem>>>(x, hidden, cost, Wo, Wh, out);
}

// round 14
// speedup vs baseline: 1.3809x; 1.3809x over previous
#include <cuda_runtime.h>
#include <cstdint>

// Problem constants
#define T_STEPS 2048
#define B_TOT   256
#define H_DIM   512
#define D_IN    529
#define KPAD    544            // padded K cols = 34 k16-steps
#define KSTEPS  34
#define ROWS_PER_CTA 64
#define B_PER_CL 16
#define NCL 16
#define NTHREADS 512
#define XROW 20

// SMEM word (uint32) offsets
#define W_WORDS (2*8*KSTEPS*32*2)     // 2 terms x 8 ntiles x 34 ks x 32 lanes x 2 regs = 34816
#define A_WORDS (2*KSTEPS*32*4)       // 2 terms x 34 ks x 32 lanes x 4 regs = 8704
#define OFF_W 0
#define OFF_A (OFF_W + W_WORDS)
#define OFF_RED (OFF_A + A_WORDS)     // float[8*32*4] lane-matched partials
#define OFF_WO (OFF_RED + 1024)       // float[KPAD]
#define OFF_XC (OFF_WO + KPAD)        // float[2*16*XROW]
#define SMEM_WORDS (OFF_XC + 2*B_PER_CL*XROW)

#define W_WORD(term,nt,ks,ln,reg) (((((term)*8+(nt))*KSTEPS+(ks))*32+(ln))*2+(reg))
#define A2W(t2,ks,ln) ((((t2)*KSTEPS+(ks))*32+(ln))*4)

// f32 hidden ping-pong (for o_t and h_final)
__device__ float g_hbuf[2][B_TOT * H_DIM];
// fragment-ready bf16 2-term hidden ping-pong: [pp][cluster][term][32 blk x 32 lanes x 4 regs]
__device__ uint32_t g_hfrag[2][NCL][2][4096];

__device__ __forceinline__ uint32_t f2bf(float f) {
    uint32_t u = __float_as_uint(f);
    return (u + 0x7FFFu + ((u >> 16) & 1u)) >> 16;
}
__device__ __forceinline__ float bf2f(uint32_t b) { return __uint_as_float(b << 16); }

// pack {lo=bf16(a), hi=bf16(b)} in one HW cvt
__device__ __forceinline__ uint32_t cvt2(float a, float b) {
    uint32_t r;
    asm("cvt.rn.satfinite.bf16x2.f32 %0, %1, %2;" : "=r"(r) : "f"(b), "f"(a));
    return r;
}

__device__ __forceinline__ void mma16816(float c[4], uint4 a, uint2 b) {
    asm volatile(
        "mma.sync.aligned.m16n8k16.row.col.f32.bf16.bf16.f32 "
        "{%0,%1,%2,%3}, {%4,%5,%6,%7}, {%8,%9}, {%0,%1,%2,%3};"
        : "+f"(c[0]), "+f"(c[1]), "+f"(c[2]), "+f"(c[3])
        : "r"(a.x), "r"(a.y), "r"(a.z), "r"(a.w), "r"(b.x), "r"(b.y));
}

// split float2 into two packed bf16x2 terms
__device__ __forceinline__ void split2(float v0, float v1, uint32_t& q0, uint32_t& q1) {
    q0 = cvt2(v0, v1);
    float e0 = v0 - __uint_as_float(q0 << 16);
    float e1 = v1 - __uint_as_float(q0 & 0xFFFF0000u);
    q1 = cvt2(e0, e1);
}

extern "C" __global__ void __launch_bounds__(NTHREADS, 1) __cluster_dims__(8, 1, 1)
rnn_mma_kernel(const float* __restrict__ x,       // [B, T, 16]
               const float* __restrict__ hidden,  // [B, 512]
               const float* __restrict__ cost,    // [B, T]
               const float* __restrict__ Wo,      // [1, 529]
               const float* __restrict__ Wh,      // [512, 529]
               float* __restrict__ out)           // [B*T] outs, then [B*512] h_final
{
    extern __shared__ uint32_t smw[];
    float* red  = (float*)(smw + OFF_RED);
    float* WoS  = (float*)(smw + OFF_WO);
    float* xcb  = (float*)(smw + OFF_XC);

    const int tid   = threadIdx.x;
    const int lane  = tid & 31;
    const int w     = tid >> 5;                 // warp 0..15
    const int crank = blockIdx.x & 7;
    const int clid  = blockIdx.x >> 3;
    const int bbase = clid * B_PER_CL;
    const int row0  = crank * ROWS_PER_CTA;

    // ---- one-time: W 2-term bf16 split into fragment-ordered SMEM ----
    for (int idx = tid; idx < ROWS_PER_CTA * KPAD; idx += NTHREADS) {
        int nl = idx / KPAD, c = idx - nl * KPAD;
        float v = (c < D_IN) ? Wh[(size_t)(row0 + nl) * D_IN + c] : 0.0f;
        uint32_t b0 = f2bf(v);
        uint32_t b1 = f2bf(v - bf2f(b0));
        int nt = nl >> 3, gp = nl & 7, ks = c >> 4, kk = c & 15;
        int reg = kk >> 3, tpp = (kk & 7) >> 1, half = kk & 1, lnp = gp * 4 + tpp;
        ((uint16_t*)smw)[(OFF_W + W_WORD(0, nt, ks, lnp, reg)) * 2 + half] = (uint16_t)b0;
        ((uint16_t*)smw)[(OFF_W + W_WORD(1, nt, ks, lnp, reg)) * 2 + half] = (uint16_t)b1;
    }
    for (int idx = tid; idx < A_WORDS; idx += NTHREADS) smw[OFF_A + idx] = 0u;
    for (int idx = tid; idx < KPAD; idx += NTHREADS) WoS[idx] = (idx < D_IN) ? Wo[idx] : 0.0f;
    // f32 h0 for o_t
    for (int idx = tid; idx < 2 * H_DIM; idx += NTHREADS) {
        int bl = idx >> 9, col = idx & (H_DIM - 1);
        size_t off = (size_t)(bbase + crank * 2 + bl) * H_DIM + col;
        g_hbuf[1][off] = hidden[off];
    }
    // frag-form h0: this CTA's 64-row slice
    {
        int m = tid >> 5, n0 = (tid & 31) * 2;
        float v0 = hidden[(size_t)(bbase + m) * H_DIM + row0 + n0];
        float v1 = hidden[(size_t)(bbase + m) * H_DIM + row0 + n0 + 1];
        uint32_t q0, q1;
        split2(v0, v1, q0, q1);
        int lane2 = (m & 7) * 4 + ((n0 >> 1) & 3);
        int rr = (m >> 3) | (((n0 >> 3) & 1) << 1);
        int widx = (row0 >> 4) * 128 + (((n0 >> 4) * 32 + lane2) * 4 + rr);
        g_hfrag[1][clid][0][widx] = q0;
        g_hfrag[1][clid][1][widx] = q1;
    }
    // x/cost t=0
    if (tid < 128) {
        int b = tid >> 3, q = tid & 7;
        const float* xp = x + ((size_t)(bbase + b) * T_STEPS) * 16;
        xcb[b * XROW + 2 * q]     = __ldg(xp + 2 * q);
        xcb[b * XROW + 2 * q + 1] = __ldg(xp + 2 * q + 1);
        if (q == 0) xcb[b * XROW + 16] = __ldg(cost + (size_t)(bbase + b) * T_STEPS);
    }
    __syncthreads();
    asm volatile("barrier.cluster.arrive.aligned;" ::: "memory");
    asm volatile("barrier.cluster.wait.aligned;"   ::: "memory");

    const int nt  = w & 7;        // compute: n-tile (8 rows)
    const int kh2 = w >> 3;       // compute: k-half

    for (int t = 0; t < T_STEPS; ++t) {
        const int ppr = (t + 1) & 1, ppw = t & 1, cur = t & 1;
        const float* xcc = xcb + cur * B_PER_CL * XROW;

        // ---- phase A: staging copy, all 512 threads (2048 uint4 = 4/thread) ----
        {
            const uint4* gsrc = (const uint4*)g_hfrag[ppr][clid];
            uint4 v[4];
            #pragma unroll
            for (int i = 0; i < 4; ++i) v[i] = __ldcg(gsrc + tid + 512 * i);
            #pragma unroll
            for (int i = 0; i < 4; ++i) {
                int q = tid + 512 * i;
                int t2 = q >> 10, qq = q & 1023;
                *(uint4*)&smw[OFF_A + (t2 * KSTEPS + 1) * 128 + qq * 4] = v[i];
            }
        }
        // x frags (ks0) and cost frags (ks33)
        if (tid < 128) {
            int m = tid >> 3, p = tid & 7;
            uint32_t q0, q1;
            split2(xcc[m * XROW + 2 * p], xcc[m * XROW + 2 * p + 1], q0, q1);
            int lane2 = (m & 7) * 4 + (p & 3);
            int rr = (m >> 3) | ((p >> 2) << 1);
            int wi = lane2 * 4 + rr;
            smw[OFF_A + wi] = q0;
            smw[OFF_A + KSTEPS * 128 + wi] = q1;
        } else if (tid < 144) {
            int m = tid - 128;
            uint32_t q0, q1;
            split2(xcc[m * XROW + 16], 0.0f, q0, q1);
            int wi = 33 * 128 + ((m & 7) * 4) * 4 + (m >> 3);
            smw[OFF_A + wi] = q0;
            smw[OFF_A + KSTEPS * 128 + wi] = q1;
        }
        __syncthreads();

        // ---- phase B: mma, 16 warps = n-tile x k-half; 17 ksteps x 4 indep chains ----
        float a00[4] = {0,0,0,0}, a01[4] = {0,0,0,0}, a10[4] = {0,0,0,0}, a11[4] = {0,0,0,0};
        #pragma unroll
        for (int s = 0; s < 17; ++s) {
            int ks = kh2 * 17 + s;
            uint4 I0 = *(const uint4*)&smw[OFF_A + A2W(0, ks, lane)];
            uint4 I1 = *(const uint4*)&smw[OFF_A + A2W(1, ks, lane)];
            uint2 W0 = *(const uint2*)&smw[OFF_W + W_WORD(0, nt, ks, lane, 0)];
            uint2 W1 = *(const uint2*)&smw[OFF_W + W_WORD(1, nt, ks, lane, 0)];
            mma16816(a00, I0, W0);
            mma16816(a10, I1, W0);
            mma16816(a01, I0, W1);
            mma16816(a11, I1, W1);
        }
        float s4[4];
        #pragma unroll
        for (int i = 0; i < 4; ++i)
            s4[i] = (a00[i] + a01[i]) + (a10[i] + a11[i]);

        if (kh2 == 0) {
            // lane-matched partial handoff (no transpose)
            *(float4*)&red[(nt * 32 + lane) * 4] = make_float4(s4[0], s4[1], s4[2], s4[3]);
        }
        __syncthreads();

        // ---- phase C ----
        if (kh2 == 1) {
            // combine partials at identical fragment coords, publish directly
            float4 p = *(const float4*)&red[(nt * 32 + lane) * 4];
            s4[0] += p.x; s4[1] += p.y; s4[2] += p.z; s4[3] += p.w;

            int b = lane >> 2, j = lane & 3;
            uint32_t t0a, t1a, t0b, t1b;
            split2(s4[0], s4[1], t0a, t1a);    // batch b,   cols 2j,2j+1
            split2(s4[2], s4[3], t0b, t1b);    // batch b+8
            int base = ((crank * 4 + (nt >> 1)) * 32 + lane) * 4 + (nt & 1) * 2;
            __stcg((uint2*)&g_hfrag[ppw][clid][0][base], make_uint2(t0a, t0b));
            __stcg((uint2*)&g_hfrag[ppw][clid][1][base], make_uint2(t1a, t1b));

            float* hdst = (t == T_STEPS - 1) ? (out + (size_t)B_TOT * T_STEPS) : g_hbuf[ppw];
            int col = row0 + nt * 8 + 2 * j;
            __stcg((float2*)(hdst + (size_t)(bbase + b) * H_DIM + col),     make_float2(s4[0], s4[1]));
            __stcg((float2*)(hdst + (size_t)(bbase + b + 8) * H_DIM + col), make_float2(s4[2], s4[3]));
        } else if (w == 0) {
            // o_t (pre-update h, f32)
            int bo = 2 * crank + (lane >> 4), li = lane & 15;
            const float* hrow = g_hbuf[ppr] + (size_t)(bbase + bo) * H_DIM;
            float r = 0.0f;
            #pragma unroll
            for (int j = 0; j < KSTEPS; ++j) {
                int c = li + 16 * j;
                float v;
                if (c < 16)        v = xcc[bo * XROW + c];
                else if (c < 528)  v = __ldcg(hrow + (c - 16));
                else if (c == 528) v = xcc[bo * XROW + 16];
                else               v = 0.0f;
                r += WoS[c] * v;
            }
            r += __shfl_xor_sync(0xffffffffu, r, 1);
            r += __shfl_xor_sync(0xffffffffu, r, 2);
            r += __shfl_xor_sync(0xffffffffu, r, 4);
            r += __shfl_xor_sync(0xffffffffu, r, 8);
            if (li == 0) out[(size_t)(bbase + bo) * T_STEPS + t] = r;
        } else if (w >= 1 && w <= 4) {
            // prefetch x/cost for t+1
            int t2 = tid - 32;
            if (t2 < 128 && t + 1 < T_STEPS) {
                int b = t2 >> 3, q = t2 & 7;
                float* dst = xcb + ((t + 1) & 1) * B_PER_CL * XROW + b * XROW;
                const float* xp = x + ((size_t)(bbase + b) * T_STEPS + (t + 1)) * 16;
                dst[2 * q]     = __ldg(xp + 2 * q);
                dst[2 * q + 1] = __ldg(xp + 2 * q + 1);
                if (q == 0) dst[16] = __ldg(cost + (size_t)(bbase + b) * T_STEPS + (t + 1));
            }
        }

        // ---- cluster barrier: publish h_{t+1} before next step reads ----
        asm volatile("barrier.cluster.arrive.aligned;" ::: "memory");
        asm volatile("barrier.cluster.wait.aligned;"   ::: "memory");
    }
}

extern "C" void kernel_launch(void* const* d_in, const int* in_sizes, int n_in,
                              void* d_out, int out_size) {
    const float* x      = (const float*)d_in[0];
    const float* hidden = (const float*)d_in[1];
    const float* cost   = (const float*)d_in[2];
    const float* Wo     = (const float*)d_in[3];
    const float* Wh     = (const float*)d_in[4];
    float* out = (float*)d_out;

    size_t smem = (size_t)SMEM_WORDS * 4;   // ~179 KB
    cudaFuncSetAttribute(rnn_mma_kernel, cudaFuncAttributeMaxDynamicSharedMemorySize, (int)smem);
    rnn_mma_kernel<<<128, NTHREADS, smem>>>(x, hidden, cost, Wo, Wh, out);
}

// round 15
// speedup vs baseline: 1.6610x; 1.2028x over previous
#include <cuda_runtime.h>
#include <cstdint>

// Problem constants
#define T_STEPS 2048
#define B_TOT   256
#define H_DIM   512
#define D_IN    529
#define KPAD    544            // padded K cols = 34 k16-steps
#define KSTEPS  34
#define ROWS_PER_CTA 64
#define B_PER_CL 16
#define NCL 16
#define NTHREADS 512
#define XROW 20

// SMEM word (uint32) offsets
#define W_WORDS (8*KSTEPS*32*4)       // 8 ntiles x 34 ks x 32 lanes x {t0r0,t0r1,t1r0,t1r1}
#define A_WORDS (2*KSTEPS*32*4)       // per group: 2 terms x 34 ks x 32 lanes x 4 regs = 8704
#define OFF_W 0
#define OFF_A0 (OFF_W + W_WORDS)
#define OFF_A1 (OFF_A0 + A_WORDS)
#define OFF_RED (OFF_A1 + A_WORDS)    // float[8*32*4] lane-matched partials
#define OFF_WO (OFF_RED + 1024)       // float[KPAD]
#define OFF_XC (OFF_WO + KPAD)        // float[2 groups][2 pp][16][XROW] = 1280
#define SMEM_WORDS (OFF_XC + 2*2*B_PER_CL*XROW)

#define WP_WORD(nt,ks,ln) ((((nt)*KSTEPS+(ks))*32+(ln))*4)
#define A2W(t2,ks,ln) ((((t2)*KSTEPS+(ks))*32+(ln))*4)

// fragment-ready bf16 2-term hidden ping-pong: [pp][group][term][32 blk x 32 lanes x 4 regs]
__device__ uint32_t g_hfrag[2][NCL][2][4096];

__device__ __forceinline__ uint32_t f2bf(float f) {
    uint32_t u = __float_as_uint(f);
    return (u + 0x7FFFu + ((u >> 16) & 1u)) >> 16;
}
__device__ __forceinline__ float bf2f(uint32_t b) { return __uint_as_float(b << 16); }

__device__ __forceinline__ uint32_t cvt2(float a, float b) {
    uint32_t r;
    asm("cvt.rn.satfinite.bf16x2.f32 %0, %1, %2;" : "=r"(r) : "f"(b), "f"(a));
    return r;
}

__device__ __forceinline__ void mma16816(float c[4], uint4 a, uint2 b) {
    asm volatile(
        "mma.sync.aligned.m16n8k16.row.col.f32.bf16.bf16.f32 "
        "{%0,%1,%2,%3}, {%4,%5,%6,%7}, {%8,%9}, {%0,%1,%2,%3};"
        : "+f"(c[0]), "+f"(c[1]), "+f"(c[2]), "+f"(c[3])
        : "r"(a.x), "r"(a.y), "r"(a.z), "r"(a.w), "r"(b.x), "r"(b.y));
}

__device__ __forceinline__ void split2(float v0, float v1, uint32_t& q0, uint32_t& q1) {
    q0 = cvt2(v0, v1);
    float e0 = v0 - __uint_as_float(q0 << 16);
    float e1 = v1 - __uint_as_float(q0 & 0xFFFF0000u);
    q1 = cvt2(e0, e1);
}

extern "C" __global__ void __launch_bounds__(NTHREADS, 1) __cluster_dims__(8, 1, 1)
rnn_mma_kernel(const float* __restrict__ x,       // [B, T, 16]
               const float* __restrict__ hidden,  // [B, 512]
               const float* __restrict__ cost,    // [B, T]
               const float* __restrict__ Wo,      // [1, 529]
               const float* __restrict__ Wh,      // [512, 529]
               float* __restrict__ out)           // [B*T] outs, then [B*512] h_final
{
    extern __shared__ uint32_t smw[];
    float* red  = (float*)(smw + OFF_RED);
    float* WoS  = (float*)(smw + OFF_WO);
    float* xcb  = (float*)(smw + OFF_XC);

    const int tid   = threadIdx.x;
    const int lane  = tid & 31;
    const int w     = tid >> 5;                 // warp 0..15
    const int crank = blockIdx.x & 7;
    const int cl    = blockIdx.x >> 3;          // cluster 0..7 (2 groups each)
    const int row0  = crank * ROWS_PER_CTA;

    // ---- one-time: W 2-term bf16 split, packed fragment order ----
    for (int idx = tid; idx < ROWS_PER_CTA * KPAD; idx += NTHREADS) {
        int nl = idx / KPAD, c = idx - nl * KPAD;
        float v = (c < D_IN) ? Wh[(size_t)(row0 + nl) * D_IN + c] : 0.0f;
        uint32_t b0 = f2bf(v);
        uint32_t b1 = f2bf(v - bf2f(b0));
        int nt = nl >> 3, gp = nl & 7, ks = c >> 4, kk = c & 15;
        int reg = kk >> 3, tpp = (kk & 7) >> 1, half = kk & 1, lnp = gp * 4 + tpp;
        ((uint16_t*)smw)[(OFF_W + WP_WORD(nt, ks, lnp) + 0 + reg) * 2 + half] = (uint16_t)b0;
        ((uint16_t*)smw)[(OFF_W + WP_WORD(nt, ks, lnp) + 2 + reg) * 2 + half] = (uint16_t)b1;
    }
    for (int idx = tid; idx < 2 * A_WORDS; idx += NTHREADS) smw[OFF_A0 + idx] = 0u;
    for (int idx = tid; idx < KPAD; idx += NTHREADS) WoS[idx] = (idx < D_IN) ? Wo[idx] : 0.0f;

    // frag-form h0 for both groups (this CTA's 64-row slice)
    #pragma unroll
    for (int g = 0; g < 2; ++g) {
        int gid = 2 * cl + g, bb = gid * B_PER_CL;
        int m = tid >> 5, n0 = (tid & 31) * 2;
        float v0 = hidden[(size_t)(bb + m) * H_DIM + row0 + n0];
        float v1 = hidden[(size_t)(bb + m) * H_DIM + row0 + n0 + 1];
        uint32_t q0, q1;
        split2(v0, v1, q0, q1);
        int lane2 = (m & 7) * 4 + ((n0 >> 1) & 3);
        int rr = (m >> 3) | (((n0 >> 3) & 1) << 1);
        int widx = (row0 >> 4) * 128 + (((n0 >> 4) * 32 + lane2) * 4 + rr);
        g_hfrag[1][gid][0][widx] = q0;
        g_hfrag[1][gid][1][widx] = q1;
    }
    // x/cost t=0 for both groups
    if (tid < 128) {
        int b = tid >> 3, q = tid & 7;
        #pragma unroll
        for (int g = 0; g < 2; ++g) {
            int bb = (2 * cl + g) * B_PER_CL;
            const float* xp = x + ((size_t)(bb + b) * T_STEPS) * 16;
            float* dst = xcb + (g * 2) * B_PER_CL * XROW + b * XROW;
            dst[2 * q]     = __ldg(xp + 2 * q);
            dst[2 * q + 1] = __ldg(xp + 2 * q + 1);
            if (q == 0) dst[16] = __ldg(cost + (size_t)(bb + b) * T_STEPS);
        }
    }
    __syncthreads();
    asm volatile("barrier.cluster.arrive.aligned;" ::: "memory");
    asm volatile("barrier.cluster.wait.aligned;"   ::: "memory");

    const int nt  = w & 7;        // n-tile (8 rows)
    const int kh2 = w >> 3;       // k-half

    for (int t = 0; t < T_STEPS; ++t) {
        const int ppr = (t + 1) & 1, ppw = t & 1, cur = t & 1;

        #pragma unroll
        for (int g = 0; g < 2; ++g) {
            const int gid   = 2 * cl + g;
            const int bbase = gid * B_PER_CL;
            const int OFF_Ag = (g == 0) ? OFF_A0 : OFF_A1;
            const float* xcc = xcb + (g * 2 + cur) * B_PER_CL * XROW;

            // ---- phase A: staging copy + x/cost frags + prefetch issue ----
            {
                const uint4* gsrc = (const uint4*)g_hfrag[ppr][gid];
                uint4 v[4];
                #pragma unroll
                for (int i = 0; i < 4; ++i) v[i] = __ldcg(gsrc + tid + 512 * i);
                #pragma unroll
                for (int i = 0; i < 4; ++i) {
                    int q = tid + 512 * i;
                    int t2 = q >> 10, qq = q & 1023;
                    *(uint4*)&smw[OFF_Ag + (t2 * KSTEPS + 1) * 128 + qq * 4] = v[i];
                }
            }
            if (tid < 128) {
                int m = tid >> 3, p = tid & 7;
                uint32_t q0, q1;
                split2(xcc[m * XROW + 2 * p], xcc[m * XROW + 2 * p + 1], q0, q1);
                int lane2 = (m & 7) * 4 + (p & 3);
                int rr = (m >> 3) | ((p >> 2) << 1);
                int wi = lane2 * 4 + rr;
                smw[OFF_Ag + wi] = q0;
                smw[OFF_Ag + KSTEPS * 128 + wi] = q1;
            } else if (tid < 144) {
                int m = tid - 128;
                uint32_t q0, q1;
                split2(xcc[m * XROW + 16], 0.0f, q0, q1);
                int wi = 33 * 128 + ((m & 7) * 4) * 4 + (m >> 3);
                smw[OFF_Ag + wi] = q0;
                smw[OFF_Ag + KSTEPS * 128 + wi] = q1;
            }
            // prefetch issue (warps 12-15): x/cost t+1 into regs
            float pf0 = 0.0f, pf1 = 0.0f, pfc = 0.0f;
            int t2p = tid - 384;
            if (t2p >= 0 && t + 1 < T_STEPS) {
                int b = t2p >> 3, q = t2p & 7;
                const float* xp = x + ((size_t)(bbase + b) * T_STEPS + (t + 1)) * 16;
                pf0 = __ldg(xp + 2 * q);
                pf1 = __ldg(xp + 2 * q + 1);
                if (q == 0) pfc = __ldg(cost + (size_t)(bbase + b) * T_STEPS + (t + 1));
            }
            __syncthreads();

            // ---- phase B: mma, 16 warps = n-tile x k-half; 17 ksteps x 4 chains ----
            float a00[4] = {0,0,0,0}, a01[4] = {0,0,0,0}, a10[4] = {0,0,0,0}, a11[4] = {0,0,0,0};
            #pragma unroll
            for (int s = 0; s < 17; ++s) {
                int ks = kh2 * 17 + s;
                uint4 I0 = *(const uint4*)&smw[OFF_Ag + A2W(0, ks, lane)];
                uint4 I1 = *(const uint4*)&smw[OFF_Ag + A2W(1, ks, lane)];
                uint4 WP = *(const uint4*)&smw[OFF_W + WP_WORD(nt, ks, lane)];
                uint2 W0 = make_uint2(WP.x, WP.y);
                uint2 W1 = make_uint2(WP.z, WP.w);
                mma16816(a00, I0, W0);
                mma16816(a10, I1, W0);
                mma16816(a01, I0, W1);
                mma16816(a11, I1, W1);
            }
            float s4[4];
            #pragma unroll
            for (int i = 0; i < 4; ++i)
                s4[i] = (a00[i] + a01[i]) + (a10[i] + a11[i]);

            if (kh2 == 0)
                *(float4*)&red[(nt * 32 + lane) * 4] = make_float4(s4[0], s4[1], s4[2], s4[3]);
            __syncthreads();

            // ---- phase C ----
            if (kh2 == 1) {
                float4 p = *(const float4*)&red[(nt * 32 + lane) * 4];
                s4[0] += p.x; s4[1] += p.y; s4[2] += p.z; s4[3] += p.w;

                int b = lane >> 2, j = lane & 3;
                uint32_t t0a, t1a, t0b, t1b;
                split2(s4[0], s4[1], t0a, t1a);
                split2(s4[2], s4[3], t0b, t1b);
                int base = ((crank * 4 + (nt >> 1)) * 32 + lane) * 4 + (nt & 1) * 2;
                __stcg((uint2*)&g_hfrag[ppw][gid][0][base], make_uint2(t0a, t0b));
                __stcg((uint2*)&g_hfrag[ppw][gid][1][base], make_uint2(t1a, t1b));

                if (t == T_STEPS - 1) {
                    float* hdst = out + (size_t)B_TOT * T_STEPS;
                    int col = row0 + nt * 8 + 2 * j;
                    __stcg((float2*)(hdst + (size_t)(bbase + b) * H_DIM + col),     make_float2(s4[0], s4[1]));
                    __stcg((float2*)(hdst + (size_t)(bbase + b + 8) * H_DIM + col), make_float2(s4[2], s4[3]));
                }
                // prefetch STS (warps 12-15 are kh2==1)
                if (t2p >= 0 && t + 1 < T_STEPS) {
                    int bb2 = t2p >> 3, q = t2p & 7;
                    float* dst = xcb + (g * 2 + ((t + 1) & 1)) * B_PER_CL * XROW + bb2 * XROW;
                    dst[2 * q]     = pf0;
                    dst[2 * q + 1] = pf1;
                    if (q == 0) dst[16] = pfc;
                }
            } else if (w == 0) {
                // o_t from SMEM A-frags (inter_t): 2 batches, 16 lanes each
                int bo = 2 * crank + (lane >> 4), li = lane & 15;
                int lane2b = (bo & 7) * 4, rrb = bo >> 3;
                float r = 0.0f;
                #pragma unroll
                for (int jj = 0; jj < 17; ++jj) {
                    int idx = li + 16 * jj;            // 0..271
                    int ks = idx >> 3, p = idx & 7;
                    int lane2 = lane2b + (p & 3);
                    int rr = rrb | ((p >> 2) << 1);
                    uint32_t w0 = smw[OFF_Ag + A2W(0, ks, lane2) + rr];
                    uint32_t w1 = smw[OFF_Ag + A2W(1, ks, lane2) + rr];
                    float lo = __uint_as_float(w0 << 16) + __uint_as_float(w1 << 16);
                    float hi = __uint_as_float(w0 & 0xFFFF0000u) + __uint_as_float(w1 & 0xFFFF0000u);
                    int c0 = ks * 16 + 2 * p;
                    float2 wo2 = *(const float2*)&WoS[c0];
                    r += wo2.x * lo + wo2.y * hi;
                }
                r += __shfl_xor_sync(0xffffffffu, r, 1);
                r += __shfl_xor_sync(0xffffffffu, r, 2);
                r += __shfl_xor_sync(0xffffffffu, r, 4);
                r += __shfl_xor_sync(0xffffffffu, r, 8);
                if (li == 0) out[(size_t)(bbase + bo) * T_STEPS + t] = r;
            }
        } // group loop

        // ---- one cluster barrier per TWO steps of work ----
        asm volatile("barrier.cluster.arrive.aligned;" ::: "memory");
        asm volatile("barrier.cluster.wait.aligned;"   ::: "memory");
    }
}

extern "C" void kernel_launch(void* const* d_in, const int* in_sizes, int n_in,
                              void* d_out, int out_size) {
    const float* x      = (const float*)d_in[0];
    const float* hidden = (const float*)d_in[1];
    const float* cost   = (const float*)d_in[2];
    const float* Wo     = (const float*)d_in[3];
    const float* Wh     = (const float*)d_in[4];
    float* out = (float*)d_out;

    size_t smem = (size_t)SMEM_WORDS * 4;   // ~220 KB
    cudaFuncSetAttribute(rnn_mma_kernel, cudaFuncAttributeMaxDynamicSharedMemorySize, (int)smem);
    rnn_mma_kernel<<<64, NTHREADS, smem>>>(x, hidden, cost, Wo, Wh, out);
}